// round 13
// baseline (speedup 1.0000x reference)
#include <cuda_runtime.h>
#include <cuda_bf16.h>

constexpr int B = 65536;
constexpr int C = 1000;
constexpr float INV_NEG_T = -1.0f / 0.3f;   // -1/TEMPERATURE

constexpr int MAIN_THREADS = 256;
constexpr int ROWS_PER_WARP = 2;
constexpr int ROWS_PER_BLOCK = (MAIN_THREADS / 32) * ROWS_PER_WARP;  // 16
constexpr int MAIN_BLOCKS = B / ROWS_PER_BLOCK;                       // 4096

// Scratch (device globals — no allocation allowed)
__device__ __align__(16) __nv_bfloat16 g_Sb[C * C];   // raw exp(-sim/T), bf16, 2 MB
__device__ float g_invZ[C];                            // 1 / sum_c exp(-sim/T)
__device__ float g_partials[MAIN_BLOCKS];

// ---------------------------------------------------------------------------
// Prep: warp per class row, no block barriers. e = exp(-sim/T) -> bf16;
// invZ[t] = 1/sum(e). 8 warps/block -> 125 blocks.
// ---------------------------------------------------------------------------
__global__ __launch_bounds__(256)
void prep_kernel(const float* __restrict__ sim) {
    const int warp = threadIdx.x >> 5;
    const int lane = threadIdx.x & 31;
    const int t = blockIdx.x * 8 + warp;       // 125 * 8 = 1000

    const float4* row = (const float4*)(sim + (size_t)t * C);
    __nv_bfloat16* dst = g_Sb + (size_t)t * C;

    float lsum = 0.0f;
    #pragma unroll
    for (int m = 0; m < 8; m++) {
        const int j = lane + m * 32;           // 250 float4 per row
        if (j < 250) {
            const float4 v = row[j];
            const float e0 = __expf(v.x * INV_NEG_T);
            const float e1 = __expf(v.y * INV_NEG_T);
            const float e2 = __expf(v.z * INV_NEG_T);
            const float e3 = __expf(v.w * INV_NEG_T);
            lsum += (e0 + e1) + (e2 + e3);
            __nv_bfloat162 p0 = __floats2bfloat162_rn(e0, e1);
            __nv_bfloat162 p1 = __floats2bfloat162_rn(e2, e3);
            uint2 packed = make_uint2(*(unsigned*)&p0, *(unsigned*)&p1);
            *(uint2*)(dst + 4 * j) = packed;
        }
    }

    #pragma unroll
    for (int o = 16; o; o >>= 1)
        lsum += __shfl_xor_sync(0xffffffffu, lsum, o);
    if (lane == 0)
        g_invZ[t] = 1.0f / lsum;
}

// ---------------------------------------------------------------------------
// Main: TWO rows per warp (independent load+compute streams -> 2x MLP).
// loss_b = log(sum exp x) - invZ[t] * dot(e_t, x).
// ---------------------------------------------------------------------------
__global__ __launch_bounds__(MAIN_THREADS)
void soft_ce_main_kernel(const float* __restrict__ logits,
                         const int* __restrict__ targets) {
    const int warp = threadIdx.x >> 5;
    const int lane = threadIdx.x & 31;
    const int r0 = (blockIdx.x * 8 + warp) * 2;   // rows r0, r0+1

    int ta = targets[r0];
    int tb = targets[r0 + 1];
    ta = (ta < 0) ? 0 : ((ta >= C) ? C - 1 : ta);
    tb = (tb < 0) ? 0 : ((tb >= C) ? C - 1 : tb);

    const float4* lpa = (const float4*)(logits + (size_t)r0 * C);
    const float4* lpb = (const float4*)(logits + (size_t)(r0 + 1) * C);
    const float4* spa = (const float4*)(g_Sb + (size_t)ta * C);
    const float4* spb = (const float4*)(g_Sb + (size_t)tb * C);
    const float invZa = g_invZ[ta];
    const float invZb = g_invZ[tb];

    float suma = 0.0f, dota = 0.0f, sumb = 0.0f, dotb = 0.0f;
    #pragma unroll
    for (int m = 0; m < 4; m++) {
        const int j = lane + m * 32;              // 125 bf16-float4 per row
        if (j < 125) {
            const float4 xa0 = lpa[2 * j];
            const float4 xa1 = lpa[2 * j + 1];
            const float4 xb0 = lpb[2 * j];
            const float4 xb1 = lpb[2 * j + 1];
            const float4 sa = spa[j];
            const float4 sb = spb[j];

            {
                const __nv_bfloat162* p = (const __nv_bfloat162*)&sa;
                const float2 s0 = __bfloat1622float2(p[0]);
                const float2 s1 = __bfloat1622float2(p[1]);
                const float2 s2 = __bfloat1622float2(p[2]);
                const float2 s3 = __bfloat1622float2(p[3]);
                suma += __expf(xa0.x) + __expf(xa0.y) + __expf(xa0.z) + __expf(xa0.w)
                      + __expf(xa1.x) + __expf(xa1.y) + __expf(xa1.z) + __expf(xa1.w);
                dota += s0.x * xa0.x + s0.y * xa0.y + s1.x * xa0.z + s1.y * xa0.w
                      + s2.x * xa1.x + s2.y * xa1.y + s3.x * xa1.z + s3.y * xa1.w;
            }
            {
                const __nv_bfloat162* p = (const __nv_bfloat162*)&sb;
                const float2 s0 = __bfloat1622float2(p[0]);
                const float2 s1 = __bfloat1622float2(p[1]);
                const float2 s2 = __bfloat1622float2(p[2]);
                const float2 s3 = __bfloat1622float2(p[3]);
                sumb += __expf(xb0.x) + __expf(xb0.y) + __expf(xb0.z) + __expf(xb0.w)
                      + __expf(xb1.x) + __expf(xb1.y) + __expf(xb1.z) + __expf(xb1.w);
                dotb += s0.x * xb0.x + s0.y * xb0.y + s1.x * xb0.z + s1.y * xb0.w
                      + s2.x * xb1.x + s2.y * xb1.y + s3.x * xb1.z + s3.y * xb1.w;
            }
        }
    }

    #pragma unroll
    for (int o = 16; o; o >>= 1) {
        suma += __shfl_xor_sync(0xffffffffu, suma, o);
        dota += __shfl_xor_sync(0xffffffffu, dota, o);
        sumb += __shfl_xor_sync(0xffffffffu, sumb, o);
        dotb += __shfl_xor_sync(0xffffffffu, dotb, o);
    }

    __shared__ float wsum[8];
    if (lane == 0)
        wsum[warp] = (__logf(suma) - dota * invZa)
                   + (__logf(sumb) - dotb * invZb);
    __syncthreads();

    if (threadIdx.x == 0) {
        float acc = 0.0f;
        #pragma unroll
        for (int w = 0; w < 8; w++) acc += wsum[w];
        g_partials[blockIdx.x] = acc;
    }
}

// ---------------------------------------------------------------------------
// Final reduce: 4096 partials -> mean loss.
// ---------------------------------------------------------------------------
__global__ __launch_bounds__(1024)
void final_reduce_kernel(float* __restrict__ out) {
    __shared__ double red[1024];
    double acc = 0.0;
    for (int i = threadIdx.x; i < MAIN_BLOCKS; i += 1024)
        acc += (double)g_partials[i];
    red[threadIdx.x] = acc;
    __syncthreads();
    for (int s = 512; s > 0; s >>= 1) {
        if (threadIdx.x < s) red[threadIdx.x] += red[threadIdx.x + s];
        __syncthreads();
    }
    if (threadIdx.x == 0)
        out[0] = (float)(red[0] / (double)B);
}

// ---------------------------------------------------------------------------
extern "C" void kernel_launch(void* const* d_in, const int* in_sizes, int n_in,
                              void* d_out, int out_size) {
    const float* logits  = (const float*)d_in[0];
    const int*   targets = (const int*)d_in[1];
    const float* sim     = (const float*)d_in[2];
    float* out = (float*)d_out;

    prep_kernel<<<125, 256>>>(sim);
    soft_ce_main_kernel<<<MAIN_BLOCKS, MAIN_THREADS>>>(logits, targets);
    final_reduce_kernel<<<1, 1024>>>(out);
}

// round 15
// speedup vs baseline: 1.0697x; 1.0697x over previous
#include <cuda_runtime.h>
#include <cuda_bf16.h>

constexpr int B = 65536;
constexpr int C = 1000;
constexpr float INV_NEG_T = -1.0f / 0.3f;   // -1/TEMPERATURE

constexpr int MAIN_THREADS = 256;
constexpr int WARPS_PER_BLOCK = MAIN_THREADS / 32;
constexpr int MAIN_BLOCKS = B / WARPS_PER_BLOCK;   // 8192

// Scratch (device globals — no allocation allowed)
__device__ __align__(16) __nv_bfloat16 g_Sb[C * C];   // raw exp(-sim/T), bf16, 2 MB
__device__ float g_invZ[C];                            // 1 / sum_c exp(-sim/T)
__device__ float g_partials[MAIN_BLOCKS];
__device__ unsigned g_done = 0;                        // last-block ticket (self-resetting)

// ---------------------------------------------------------------------------
// Prep: block per class row (R8 shape, measured 6.0us), shfl-based reduction.
// e = exp(-sim/T) -> bf16 store; invZ[t] = 1/sum(e).
// ---------------------------------------------------------------------------
__global__ __launch_bounds__(256)
void prep_kernel(const float* __restrict__ sim) {
    const int t = blockIdx.x;
    const int warp = threadIdx.x >> 5;
    const int lane = threadIdx.x & 31;
    const float* row = sim + (size_t)t * C;
    __shared__ float wred[8];

    float lsum = 0.0f;
    const int i0 = threadIdx.x * 4;            // 250 active threads x float4
    if (i0 < C) {
        const float4 v = *(const float4*)(row + i0);
        const float e0 = __expf(v.x * INV_NEG_T);
        const float e1 = __expf(v.y * INV_NEG_T);
        const float e2 = __expf(v.z * INV_NEG_T);
        const float e3 = __expf(v.w * INV_NEG_T);
        lsum = (e0 + e1) + (e2 + e3);
        __nv_bfloat162 p0 = __floats2bfloat162_rn(e0, e1);
        __nv_bfloat162 p1 = __floats2bfloat162_rn(e2, e3);
        uint2 packed = make_uint2(*(unsigned*)&p0, *(unsigned*)&p1);
        *(uint2*)(g_Sb + (size_t)t * C + i0) = packed;
    }

    #pragma unroll
    for (int o = 16; o; o >>= 1)
        lsum += __shfl_xor_sync(0xffffffffu, lsum, o);
    if (lane == 0) wred[warp] = lsum;
    __syncthreads();

    if (warp == 0) {
        float s = (lane < 8) ? wred[lane] : 0.0f;
        #pragma unroll
        for (int o = 4; o; o >>= 1)
            s += __shfl_xor_sync(0xffffffffu, s, o);
        if (lane == 0)
            g_invZ[t] = 1.0f / s;
    }
}

// ---------------------------------------------------------------------------
// Main: one warp per row (R8 shape). loss_b = log(sum exp x) - invZ[t]*dot.
// Logits streamed with __ldcs (evict-first: keep S table hot in L2).
// Last finishing block reduces all partials -> out (no 3rd kernel).
// ---------------------------------------------------------------------------
__global__ __launch_bounds__(MAIN_THREADS)
void soft_ce_main_kernel(const float* __restrict__ logits,
                         const int* __restrict__ targets,
                         float* __restrict__ out) {
    const int warp = threadIdx.x >> 5;
    const int lane = threadIdx.x & 31;
    const int row = blockIdx.x * WARPS_PER_BLOCK + warp;

    int t = targets[row];
    t = (t < 0) ? 0 : ((t >= C) ? C - 1 : t);

    const float4* lp = (const float4*)(logits + (size_t)row * C);
    const float4* sp = (const float4*)(g_Sb + (size_t)t * C);
    const float invZ = g_invZ[t];

    float sum = 0.0f, dot = 0.0f;
    #pragma unroll
    for (int m = 0; m < 4; m++) {
        const int j = lane + m * 32;              // 125 bf16-float4 per row
        if (j < 125) {
            const float4 x0 = __ldcs(lp + 2 * j);
            const float4 x1 = __ldcs(lp + 2 * j + 1);
            const float4 sraw = sp[j];
            const __nv_bfloat162* sb = (const __nv_bfloat162*)&sraw;
            const float2 s0 = __bfloat1622float2(sb[0]);
            const float2 s1 = __bfloat1622float2(sb[1]);
            const float2 s2 = __bfloat1622float2(sb[2]);
            const float2 s3 = __bfloat1622float2(sb[3]);

            sum += __expf(x0.x) + __expf(x0.y) + __expf(x0.z) + __expf(x0.w)
                 + __expf(x1.x) + __expf(x1.y) + __expf(x1.z) + __expf(x1.w);
            dot += s0.x * x0.x + s0.y * x0.y + s1.x * x0.z + s1.y * x0.w
                 + s2.x * x1.x + s2.y * x1.y + s3.x * x1.z + s3.y * x1.w;
        }
    }

    #pragma unroll
    for (int o = 16; o; o >>= 1) {
        sum += __shfl_xor_sync(0xffffffffu, sum, o);
        dot += __shfl_xor_sync(0xffffffffu, dot, o);
    }

    __shared__ float wsum[WARPS_PER_BLOCK];
    __shared__ unsigned s_ticket;
    if (lane == 0)
        wsum[warp] = __logf(sum) - dot * invZ;
    __syncthreads();

    if (threadIdx.x == 0) {
        float acc = 0.0f;
        #pragma unroll
        for (int w = 0; w < WARPS_PER_BLOCK; w++) acc += wsum[w];
        g_partials[blockIdx.x] = acc;
        __threadfence();
        s_ticket = atomicAdd(&g_done, 1u);
    }
    __syncthreads();

    // Last block to finish reduces all partials (deterministic fixed-stride order).
    if (s_ticket == MAIN_BLOCKS - 1) {
        __shared__ double dred[MAIN_THREADS];
        double acc = 0.0;
        for (int i = threadIdx.x; i < MAIN_BLOCKS; i += MAIN_THREADS)
            acc += (double)g_partials[i];
        dred[threadIdx.x] = acc;
        __syncthreads();
        #pragma unroll
        for (int s = MAIN_THREADS / 2; s > 0; s >>= 1) {
            if (threadIdx.x < s) dred[threadIdx.x] += dred[threadIdx.x + s];
            __syncthreads();
        }
        if (threadIdx.x == 0) {
            out[0] = (float)(dred[0] / (double)B);
            g_done = 0;                     // reset for next graph replay
        }
    }
}

// ---------------------------------------------------------------------------
extern "C" void kernel_launch(void* const* d_in, const int* in_sizes, int n_in,
                              void* d_out, int out_size) {
    const float* logits  = (const float*)d_in[0];
    const int*   targets = (const int*)d_in[1];
    const float* sim     = (const float*)d_in[2];
    float* out = (float*)d_out;

    prep_kernel<<<C, 256>>>(sim);
    soft_ce_main_kernel<<<MAIN_BLOCKS, MAIN_THREADS>>>(logits, targets, out);
}